// round 3
// baseline (speedup 1.0000x reference)
#include <cuda_runtime.h>
#include <cuda_bf16.h>

// GCN: h1 = relu(A_hat @ (x@W1) + b1); h2 = A_hat @ (h1@W2) + b2
// out[g] = mean_{i in g} dot(h2[i], Wl) + bl
//        = mean(dot(agg2[i], Wl)) + dot(b2, Wl) + bl
// A_hat = D^-1/2 (A + I) D^-1/2 with deg over dst (+1 self loop).

#define NMAX 100000
#define GMAX 512
#define FEAT 128

__device__ float g_bufA[(size_t)NMAX * FEAT];
__device__ float g_bufB[(size_t)NMAX * FEAT];
__device__ float g_bufC[(size_t)NMAX * FEAT];
__device__ float g_deg[NMAX];
__device__ float g_dinv[NMAX];
__device__ float g_gsum[GMAX];
__device__ float g_cnt[GMAX];

// ---------------------------------------------------------------------------
__global__ void k_init(int n) {
    int i = blockIdx.x * blockDim.x + threadIdx.x;
    if (i < n) g_deg[i] = 1.0f;             // self loop
    if (i < GMAX) { g_gsum[i] = 0.0f; g_cnt[i] = 0.0f; }
}

__global__ void k_deg(const int* __restrict__ dst, int E,
                      const int* __restrict__ batch, int n) {
    int stride = gridDim.x * blockDim.x;
    int t = blockIdx.x * blockDim.x + threadIdx.x;
    for (int e = t; e < E; e += stride)
        atomicAdd(&g_deg[dst[e]], 1.0f);
    for (int i = t; i < n; i += stride)
        atomicAdd(&g_cnt[batch[i]], 1.0f);
}

__global__ void k_dinv(int n) {
    int i = blockIdx.x * blockDim.x + threadIdx.x;
    if (i < n) g_dinv[i] = rsqrtf(g_deg[i]);
}

// ---------------------------------------------------------------------------
// SGEMM: C[M,128] = A[M,128] @ B[128,128], fp32. BM=128,BN=128,BK=8,TM=TN=8.
__global__ __launch_bounds__(256) void k_sgemm(const float* __restrict__ A,
                                               const float* __restrict__ B,
                                               float* __restrict__ C, int M) {
    __shared__ float As[8][128];
    __shared__ float Bs[8][128];
    const int tid = threadIdx.x;
    const int block_row = blockIdx.x * 128;
    const int tr = tid / 16;          // 0..15 -> row group (8 rows)
    const int tc = tid % 16;          // 0..15 -> col group (8 cols)

    const int aRow = tid >> 1;              // 0..127
    const int aCol = (tid & 1) * 4;         // 0 or 4
    const int bRow = tid >> 5;              // 0..7
    const int bCol = (tid & 31) * 4;        // 0..124

    float acc[8][8];
#pragma unroll
    for (int i = 0; i < 8; i++)
#pragma unroll
        for (int j = 0; j < 8; j++) acc[i][j] = 0.0f;

    for (int k0 = 0; k0 < 128; k0 += 8) {
        float4 av = make_float4(0.f, 0.f, 0.f, 0.f);
        int gr = block_row + aRow;
        if (gr < M) av = *(const float4*)(A + (size_t)gr * 128 + k0 + aCol);
        As[aCol + 0][aRow] = av.x;
        As[aCol + 1][aRow] = av.y;
        As[aCol + 2][aRow] = av.z;
        As[aCol + 3][aRow] = av.w;
        *(float4*)&Bs[bRow][bCol] =
            *(const float4*)(B + (size_t)(k0 + bRow) * 128 + bCol);
        __syncthreads();

#pragma unroll
        for (int k = 0; k < 8; k++) {
            float a[8], b[8];
#pragma unroll
            for (int i = 0; i < 8; i++) a[i] = As[k][tr * 8 + i];
#pragma unroll
            for (int j = 0; j < 8; j++) b[j] = Bs[k][tc * 8 + j];
#pragma unroll
            for (int i = 0; i < 8; i++)
#pragma unroll
                for (int j = 0; j < 8; j++) acc[i][j] += a[i] * b[j];
        }
        __syncthreads();
    }

#pragma unroll
    for (int i = 0; i < 8; i++) {
        int row = block_row + tr * 8 + i;
        if (row < M) {
            float* cp = C + (size_t)row * 128 + tc * 8;
            *(float4*)cp       = make_float4(acc[i][0], acc[i][1], acc[i][2], acc[i][3]);
            *(float4*)(cp + 4) = make_float4(acc[i][4], acc[i][5], acc[i][6], acc[i][7]);
        }
    }
}

// ---------------------------------------------------------------------------
// agg[i] = h[i] * dinv[i]^2   (self-loop term, initializes accumulator)
__global__ void k_self(const float* __restrict__ h, float* __restrict__ agg, int n) {
    int stride = gridDim.x * blockDim.x;
    int total = n * (FEAT / 4);  // float4 count
    for (int idx = blockIdx.x * blockDim.x + threadIdx.x; idx < total; idx += stride) {
        int row = idx >> 5;                // 32 float4 per row
        float d = g_dinv[row];
        float s = d * d;
        float4 v = ((const float4*)h)[idx];
        v.x *= s; v.y *= s; v.z *= s; v.w *= s;
        ((float4*)agg)[idx] = v;
    }
}

// Per-edge scatter: warp per edge, lane handles 4 feats via red.v4.f32
__global__ void k_scatter(const float* __restrict__ h, float* __restrict__ agg,
                          const int* __restrict__ src, const int* __restrict__ dst,
                          int E) {
    const int lane = threadIdx.x & 31;
    int warp = (blockIdx.x * blockDim.x + threadIdx.x) >> 5;
    int nwarps = (gridDim.x * blockDim.x) >> 5;
    for (int e = warp; e < E; e += nwarps) {
        int s = src[e];
        int d = dst[e];
        float norm = g_dinv[s] * g_dinv[d];
        float4 v = ((const float4*)(h + (size_t)s * FEAT))[lane];
        float* p = agg + (size_t)d * FEAT + lane * 4;
        asm volatile("red.global.add.v4.f32 [%0], {%1, %2, %3, %4};"
                     :: "l"(p), "f"(v.x * norm), "f"(v.y * norm),
                        "f"(v.z * norm), "f"(v.w * norm)
                     : "memory");
    }
}

// h_out = relu(agg + bias)
__global__ void k_relu_bias(const float* __restrict__ agg, float* __restrict__ out,
                            const float* __restrict__ bias, int n) {
    int stride = gridDim.x * blockDim.x;
    int total = n * (FEAT / 4);
    for (int idx = blockIdx.x * blockDim.x + threadIdx.x; idx < total; idx += stride) {
        float4 bv = ((const float4*)bias)[idx & 31];
        float4 v = ((const float4*)agg)[idx];
        v.x = fmaxf(v.x + bv.x, 0.f);
        v.y = fmaxf(v.y + bv.y, 0.f);
        v.z = fmaxf(v.z + bv.z, 0.f);
        v.w = fmaxf(v.w + bv.w, 0.f);
        ((float4*)out)[idx] = v;
    }
}

// Per-node: gsum[batch[i]] += dot(agg2[i], Wl). Warp per node.
__global__ void k_pool(const float* __restrict__ agg,
                       const int* __restrict__ batch,
                       const float* __restrict__ Wl, int n) {
    const int lane = threadIdx.x & 31;
    int warp = (blockIdx.x * blockDim.x + threadIdx.x) >> 5;
    int nwarps = (gridDim.x * blockDim.x) >> 5;
    float4 wl = ((const float4*)Wl)[lane];
    for (int i = warp; i < n; i += nwarps) {
        float4 v = ((const float4*)(agg + (size_t)i * FEAT))[lane];
        float s = v.x * wl.x + v.y * wl.y + v.z * wl.z + v.w * wl.w;
#pragma unroll
        for (int off = 16; off > 0; off >>= 1)
            s += __shfl_xor_sync(0xFFFFFFFFu, s, off);
        if (lane == 0) atomicAdd(&g_gsum[batch[i]], s);
    }
}

// out[g] = gsum[g]/max(cnt,1) + dot(b2, Wl) + bl
__global__ void k_out(const float* __restrict__ b2, const float* __restrict__ Wl,
                      const float* __restrict__ bl, float* __restrict__ out) {
    int g = blockIdx.x * blockDim.x + threadIdx.x;
    if (g < GMAX) {
        float c = 0.0f;
#pragma unroll 4
        for (int f = 0; f < FEAT; f++) c += b2[f] * Wl[f];
        out[g] = g_gsum[g] / fmaxf(g_cnt[g], 1.0f) + c + bl[0];
    }
}

// ---------------------------------------------------------------------------
extern "C" void kernel_launch(void* const* d_in, const int* in_sizes, int n_in,
                              void* d_out, int out_size) {
    const float* x     = (const float*)d_in[0];
    const int*   ei    = (const int*)d_in[1];
    const int*   batch = (const int*)d_in[3];
    const float* W1    = (const float*)d_in[4];
    const float* b1    = (const float*)d_in[5];
    const float* W2    = (const float*)d_in[6];
    const float* b2    = (const float*)d_in[7];
    const float* Wl    = (const float*)d_in[8];
    const float* bl    = (const float*)d_in[9];
    float* out = (float*)d_out;

    int n = in_sizes[0] / FEAT;
    int E = in_sizes[1] / 2;
    if (n > NMAX) n = NMAX;
    const int* src = ei;
    const int* dst = ei + E;

    float *bufA, *bufB, *bufC;
    cudaGetSymbolAddress((void**)&bufA, g_bufA);
    cudaGetSymbolAddress((void**)&bufB, g_bufB);
    cudaGetSymbolAddress((void**)&bufC, g_bufC);

    const int T = 256;
    int nBlocksN   = (n + T - 1) / T;
    int gemmBlocks = (n + 127) / 128;

    k_init<<<nBlocksN, T>>>(n);
    k_deg<<<1024, T>>>(dst, E, batch, n);
    k_dinv<<<nBlocksN, T>>>(n);

    // Layer 1
    k_sgemm<<<gemmBlocks, T>>>(x, W1, bufA, n);
    k_self<<<2048, T>>>(bufA, bufB, n);
    k_scatter<<<4096, T>>>(bufA, bufB, src, dst, E);
    k_relu_bias<<<2048, T>>>(bufB, bufA, b1, n);

    // Layer 2
    k_sgemm<<<gemmBlocks, T>>>(bufA, W2, bufB, n);
    k_self<<<2048, T>>>(bufB, bufC, n);
    k_scatter<<<4096, T>>>(bufB, bufC, src, dst, E);

    // Pool + head
    k_pool<<<1024, T>>>(bufC, batch, Wl, n);
    k_out<<<(GMAX + T - 1) / T, T>>>(b2, Wl, bl, out);
}

// round 4
// speedup vs baseline: 2.1245x; 2.1245x over previous
#include <cuda_runtime.h>
#include <cuda_bf16.h>

// GCN: h1 = relu(A_hat @ (x@W1) + b1); h2 = A_hat @ (h1@W2) + b2
// out[g] = mean(dot(agg2[i], Wl)) + dot(b2, Wl) + bl   (b2 folded into epilogue)
// A_hat = D^-1/2 (A + I) D^-1/2, deg over dst (+1 self loop).
//
// Strategy: build dst-CSR once per launch, then warp-per-node register gather
// (no fp32 atomics on feature rows). GEMMs are double-buffered fp32 SGEMM.

#define NMAX 100000
#define EMAX 1600000
#define GMAX 512
#define FEAT 128

__device__ float g_bufA[(size_t)NMAX * FEAT];
__device__ float g_bufB[(size_t)NMAX * FEAT];
__device__ float g_dinv[NMAX];
__device__ float g_gsum[GMAX];
__device__ float g_cnt[GMAX];

__device__ int g_degi[NMAX];      // incoming-edge count (no self loop)
__device__ int g_incl[NMAX];      // inclusive scan within block
__device__ int g_part[256];       // per-block partial sums
__device__ int g_rowstart[NMAX];  // exclusive prefix (CSR row offsets)
__device__ int g_cursor[NMAX];    // fill cursors
__device__ int g_csrc[EMAX];      // CSR: source node per incoming edge

// ---------------------------------------------------------------------------
__global__ void k_init(int n) {
    int i = blockIdx.x * blockDim.x + threadIdx.x;
    if (i < n) { g_degi[i] = 0; g_cursor[i] = 0; }
    if (i < GMAX) { g_gsum[i] = 0.0f; g_cnt[i] = 0.0f; }
}

__global__ void k_hist(const int* __restrict__ dst, int E,
                       const int* __restrict__ batch, int n) {
    int stride = gridDim.x * blockDim.x;
    int t = blockIdx.x * blockDim.x + threadIdx.x;
    for (int e = t; e < E; e += stride)
        atomicAdd(&g_degi[dst[e]], 1);
    for (int i = t; i < n; i += stride)
        atomicAdd(&g_cnt[batch[i]], 1.0f);
}

// Block-wise inclusive scan of g_degi (1024 elems/block)
__global__ __launch_bounds__(1024) void k_scan1(int n) {
    __shared__ int sm[1024];
    int gid = blockIdx.x * 1024 + threadIdx.x;
    int v = (gid < n) ? g_degi[gid] : 0;
    sm[threadIdx.x] = v;
    __syncthreads();
#pragma unroll
    for (int off = 1; off < 1024; off <<= 1) {
        int t = (threadIdx.x >= off) ? sm[threadIdx.x - off] : 0;
        __syncthreads();
        sm[threadIdx.x] += t;
        __syncthreads();
    }
    if (gid < n) g_incl[gid] = sm[threadIdx.x];
    if (threadIdx.x == 1023) g_part[blockIdx.x] = sm[1023];
}

// Exclusive scan of block partials (nb <= 256), single block
__global__ __launch_bounds__(256) void k_scan2(int nb) {
    __shared__ int sm[256];
    int v = (threadIdx.x < nb) ? g_part[threadIdx.x] : 0;
    sm[threadIdx.x] = v;
    __syncthreads();
#pragma unroll
    for (int off = 1; off < 256; off <<= 1) {
        int t = (threadIdx.x >= off) ? sm[threadIdx.x - off] : 0;
        __syncthreads();
        sm[threadIdx.x] += t;
        __syncthreads();
    }
    if (threadIdx.x < nb) g_part[threadIdx.x] = sm[threadIdx.x] - v;  // exclusive
}

// rowstart[i] = exclusive prefix = incl[i] - degi[i] + part[block]
__global__ void k_scan3(int n) {
    int i = blockIdx.x * blockDim.x + threadIdx.x;
    if (i < n) g_rowstart[i] = g_incl[i] - g_degi[i] + g_part[i >> 10];
}

__global__ void k_fill(const int* __restrict__ src, const int* __restrict__ dst, int E) {
    int stride = gridDim.x * blockDim.x;
    for (int e = blockIdx.x * blockDim.x + threadIdx.x; e < E; e += stride) {
        int d = dst[e];
        int pos = g_rowstart[d] + atomicAdd(&g_cursor[d], 1);
        g_csrc[pos] = src[e];
    }
}

__global__ void k_dinv(int n) {
    int i = blockIdx.x * blockDim.x + threadIdx.x;
    if (i < n) g_dinv[i] = rsqrtf(1.0f + (float)g_degi[i]);
}

// ---------------------------------------------------------------------------
// SGEMM: C[M,128] = A[M,128] @ B[128,128], fp32, double-buffered smem.
__global__ __launch_bounds__(256) void k_sgemm(const float* __restrict__ A,
                                               const float* __restrict__ B,
                                               float* __restrict__ C, int M) {
    __shared__ float As[2][8][128];
    __shared__ float Bs[2][8][128];
    const int tid = threadIdx.x;
    const int block_row = blockIdx.x * 128;
    const int tr = tid / 16;
    const int tc = tid % 16;
    const int aRow = tid >> 1;
    const int aCol = (tid & 1) * 4;
    const int bRow = tid >> 5;
    const int bCol = (tid & 31) * 4;
    const int gr = block_row + aRow;

    float acc[8][8];
#pragma unroll
    for (int i = 0; i < 8; i++)
#pragma unroll
        for (int j = 0; j < 8; j++) acc[i][j] = 0.0f;

    // prologue: tile k0=0 into buf 0
    {
        float4 av = make_float4(0.f, 0.f, 0.f, 0.f);
        if (gr < M) av = *(const float4*)(A + (size_t)gr * 128 + aCol);
        As[0][aCol + 0][aRow] = av.x;
        As[0][aCol + 1][aRow] = av.y;
        As[0][aCol + 2][aRow] = av.z;
        As[0][aCol + 3][aRow] = av.w;
        *(float4*)&Bs[0][bRow][bCol] = *(const float4*)(B + (size_t)bRow * 128 + bCol);
    }
    __syncthreads();

    int buf = 0;
#pragma unroll
    for (int k0 = 0; k0 < 128; k0 += 8) {
        if (k0 + 8 < 128) {
            float4 av = make_float4(0.f, 0.f, 0.f, 0.f);
            if (gr < M) av = *(const float4*)(A + (size_t)gr * 128 + k0 + 8 + aCol);
            As[buf ^ 1][aCol + 0][aRow] = av.x;
            As[buf ^ 1][aCol + 1][aRow] = av.y;
            As[buf ^ 1][aCol + 2][aRow] = av.z;
            As[buf ^ 1][aCol + 3][aRow] = av.w;
            *(float4*)&Bs[buf ^ 1][bRow][bCol] =
                *(const float4*)(B + (size_t)(k0 + 8 + bRow) * 128 + bCol);
        }
#pragma unroll
        for (int k = 0; k < 8; k++) {
            float a[8], b[8];
#pragma unroll
            for (int i = 0; i < 8; i++) a[i] = As[buf][k][tr * 8 + i];
#pragma unroll
            for (int j = 0; j < 8; j++) b[j] = Bs[buf][k][tc * 8 + j];
#pragma unroll
            for (int i = 0; i < 8; i++)
#pragma unroll
                for (int j = 0; j < 8; j++) acc[i][j] += a[i] * b[j];
        }
        __syncthreads();
        buf ^= 1;
    }

#pragma unroll
    for (int i = 0; i < 8; i++) {
        int row = block_row + tr * 8 + i;
        if (row < M) {
            float* cp = C + (size_t)row * 128 + tc * 8;
            *(float4*)cp       = make_float4(acc[i][0], acc[i][1], acc[i][2], acc[i][3]);
            *(float4*)(cp + 4) = make_float4(acc[i][4], acc[i][5], acc[i][6], acc[i][7]);
        }
    }
}

// ---------------------------------------------------------------------------
// Warp-per-node CSR gather. acc = h[d]*dinv[d]^2 + sum_{s in N(d)} h[s]*dinv[s]*dinv[d]
// RELU:  out[d] = relu(acc + bias)
// POOL:  gsum[batch[d]] += dot(acc, Wl)   (b2 contribution folded into k_out)
template<bool RELU, bool POOL>
__global__ void k_gather(const float* __restrict__ h, float* __restrict__ out,
                         const float* __restrict__ bias, const float* __restrict__ Wl,
                         const int* __restrict__ batch, int n) {
    const int lane = threadIdx.x & 31;
    int warp = (blockIdx.x * blockDim.x + threadIdx.x) >> 5;
    int nwarps = (gridDim.x * blockDim.x) >> 5;
    float4 wl = make_float4(0.f, 0.f, 0.f, 0.f);
    if (POOL) wl = ((const float4*)Wl)[lane];
    for (int d = warp; d < n; d += nwarps) {
        float dd = g_dinv[d];
        float4 acc = ((const float4*)(h + (size_t)d * FEAT))[lane];
        float sl = dd * dd;
        acc.x *= sl; acc.y *= sl; acc.z *= sl; acc.w *= sl;
        int r0 = g_rowstart[d];
        int r1 = r0 + g_degi[d];
        for (int r = r0; r < r1; r++) {
            int s = g_csrc[r];
            float nrm = g_dinv[s] * dd;
            float4 v = ((const float4*)(h + (size_t)s * FEAT))[lane];
            acc.x += v.x * nrm; acc.y += v.y * nrm;
            acc.z += v.z * nrm; acc.w += v.w * nrm;
        }
        if (POOL) {
            float sdot = acc.x * wl.x + acc.y * wl.y + acc.z * wl.z + acc.w * wl.w;
#pragma unroll
            for (int off = 16; off > 0; off >>= 1)
                sdot += __shfl_xor_sync(0xFFFFFFFFu, sdot, off);
            if (lane == 0) atomicAdd(&g_gsum[batch[d]], sdot);
        } else {
            float4 bv = ((const float4*)bias)[lane];
            acc.x += bv.x; acc.y += bv.y; acc.z += bv.z; acc.w += bv.w;
            if (RELU) {
                acc.x = fmaxf(acc.x, 0.f); acc.y = fmaxf(acc.y, 0.f);
                acc.z = fmaxf(acc.z, 0.f); acc.w = fmaxf(acc.w, 0.f);
            }
            ((float4*)(out + (size_t)d * FEAT))[lane] = acc;
        }
    }
}

// out[g] = gsum[g]/max(cnt,1) + dot(b2, Wl) + bl
__global__ void k_out(const float* __restrict__ b2, const float* __restrict__ Wl,
                      const float* __restrict__ bl, float* __restrict__ out) {
    int g = blockIdx.x * blockDim.x + threadIdx.x;
    if (g < GMAX) {
        float c = 0.0f;
#pragma unroll 4
        for (int f = 0; f < FEAT; f++) c += b2[f] * Wl[f];
        out[g] = g_gsum[g] / fmaxf(g_cnt[g], 1.0f) + c + bl[0];
    }
}

// ---------------------------------------------------------------------------
extern "C" void kernel_launch(void* const* d_in, const int* in_sizes, int n_in,
                              void* d_out, int out_size) {
    const float* x     = (const float*)d_in[0];
    const int*   ei    = (const int*)d_in[1];
    const int*   batch = (const int*)d_in[3];
    const float* W1    = (const float*)d_in[4];
    const float* b1    = (const float*)d_in[5];
    const float* W2    = (const float*)d_in[6];
    const float* b2    = (const float*)d_in[7];
    const float* Wl    = (const float*)d_in[8];
    const float* bl    = (const float*)d_in[9];
    float* out = (float*)d_out;

    int n = in_sizes[0] / FEAT;
    int E = in_sizes[1] / 2;
    if (n > NMAX) n = NMAX;
    if (E > EMAX) E = EMAX;
    const int* src = ei;
    const int* dst = ei + E;

    float *bufA, *bufB;
    cudaGetSymbolAddress((void**)&bufA, g_bufA);
    cudaGetSymbolAddress((void**)&bufB, g_bufB);

    const int T = 256;
    int nBlocksN   = (n + T - 1) / T;
    int gemmBlocks = (n + 127) / 128;
    int scanBlocks = (n + 1023) / 1024;   // <= 256 for NMAX

    // CSR build (once per launch)
    k_init<<<nBlocksN, T>>>(n);
    k_hist<<<1024, T>>>(dst, E, batch, n);
    k_scan1<<<scanBlocks, 1024>>>(n);
    k_scan2<<<1, 256>>>(scanBlocks);
    k_scan3<<<nBlocksN, T>>>(n);
    k_fill<<<1024, T>>>(src, dst, E);
    k_dinv<<<nBlocksN, T>>>(n);

    // Layer 1: h1 = relu(A_hat @ (x@W1) + b1)
    k_sgemm<<<gemmBlocks, T>>>(x, W1, bufA, n);
    k_gather<true, false><<<2048, T>>>(bufA, bufB, b1, nullptr, nullptr, n);

    // Layer 2 + fused pool: gsum += dot(A_hat @ (h1@W2), Wl) per graph
    k_sgemm<<<gemmBlocks, T>>>(bufB, W2, bufA, n);
    k_gather<false, true><<<2048, T>>>(bufA, nullptr, nullptr, Wl, batch, n);

    // Head
    k_out<<<(GMAX + T - 1) / T, T>>>(b2, Wl, bl, out);
}

// round 5
// speedup vs baseline: 3.2633x; 1.5361x over previous
#include <cuda_runtime.h>
#include <cuda_bf16.h>

// GCN: h1 = relu(A_hat @ (x@W1) + b1); h2 = A_hat @ (h1@W2) + b2
// out[g] = mean_i dot(h2[i], Wl) + bl
// Layer 2 is linear => with w2l = W2@Wl:
//   dot(h2[i],Wl) = (A_hat @ (h1 @ w2l))[i] + dot(b2,Wl)
// So layer 2 collapses to a scalar gather over y = h1 @ w2l, and h1 is never
// materialized: layer-1 gather epilogue emits w[d] = dinv[d]*dot(relu(acc+b1), w2l).

#define NMAX 100000
#define EMAX 1600000
#define GMAX 512
#define FEAT 128

__device__ float g_bufA[(size_t)NMAX * FEAT];   // x @ W1
__device__ float g_w[NMAX];                      // dinv[i] * dot(h1[i], w2l)
__device__ float g_dinv[NMAX];
__device__ float g_w2l[FEAT];
__device__ float g_b2wl;                         // dot(b2, Wl)
__device__ float g_gsum[GMAX];
__device__ float g_cnt[GMAX];

__device__ int g_degi[NMAX];      // incoming-edge count (no self loop)
__device__ int g_incl[NMAX];      // inclusive scan within block
__device__ int g_part[256];       // per-block partial sums
__device__ int g_rowstart[NMAX];  // CSR row offsets (exclusive prefix)
__device__ int g_cursor[NMAX];    // fill cursors
__device__ int g_csrc[EMAX];      // CSR: source node per incoming edge

// ---------------------------------------------------------------------------
__global__ void k_init(int n) {
    int i = blockIdx.x * blockDim.x + threadIdx.x;
    if (i < n) { g_degi[i] = 0; g_cursor[i] = 0; }
    if (i < GMAX) { g_gsum[i] = 0.0f; g_cnt[i] = 0.0f; }
}

__global__ void k_hist(const int* __restrict__ dst, int E,
                       const int* __restrict__ batch, int n) {
    int stride = gridDim.x * blockDim.x;
    int t = blockIdx.x * blockDim.x + threadIdx.x;
    for (int e = t; e < E; e += stride)
        atomicAdd(&g_degi[dst[e]], 1);
    for (int i = t; i < n; i += stride)
        atomicAdd(&g_cnt[batch[i]], 1.0f);
}

// w2l = W2 @ Wl ; b2wl = dot(b2, Wl). One block, 128 threads.
__global__ __launch_bounds__(128) void k_w2l(const float* __restrict__ W2,
                                             const float* __restrict__ Wl,
                                             const float* __restrict__ b2) {
    __shared__ float wls[FEAT];
    int t = threadIdx.x;
    wls[t] = Wl[t];
    __syncthreads();
    float acc = 0.0f;
    const float* row = W2 + (size_t)t * FEAT;
#pragma unroll 8
    for (int j = 0; j < FEAT; j++) acc += row[j] * wls[j];
    g_w2l[t] = acc;
    if (t == 0) {
        float c = 0.0f;
        for (int j = 0; j < FEAT; j++) c += b2[j] * wls[j];
        g_b2wl = c;
    }
}

// Block-wise inclusive scan of g_degi (1024 elems/block)
__global__ __launch_bounds__(1024) void k_scan1(int n) {
    __shared__ int sm[1024];
    int gid = blockIdx.x * 1024 + threadIdx.x;
    int v = (gid < n) ? g_degi[gid] : 0;
    sm[threadIdx.x] = v;
    __syncthreads();
#pragma unroll
    for (int off = 1; off < 1024; off <<= 1) {
        int t = (threadIdx.x >= off) ? sm[threadIdx.x - off] : 0;
        __syncthreads();
        sm[threadIdx.x] += t;
        __syncthreads();
    }
    if (gid < n) g_incl[gid] = sm[threadIdx.x];
    if (threadIdx.x == 1023) g_part[blockIdx.x] = sm[1023];
}

// Exclusive scan of block partials (nb <= 256), single block
__global__ __launch_bounds__(256) void k_scan2(int nb) {
    __shared__ int sm[256];
    int v = (threadIdx.x < nb) ? g_part[threadIdx.x] : 0;
    sm[threadIdx.x] = v;
    __syncthreads();
#pragma unroll
    for (int off = 1; off < 256; off <<= 1) {
        int t = (threadIdx.x >= off) ? sm[threadIdx.x - off] : 0;
        __syncthreads();
        sm[threadIdx.x] += t;
        __syncthreads();
    }
    if (threadIdx.x < nb) g_part[threadIdx.x] = sm[threadIdx.x] - v;  // exclusive
}

// rowstart + dinv in one pass
__global__ void k_scan3(int n) {
    int i = blockIdx.x * blockDim.x + threadIdx.x;
    if (i < n) {
        int deg = g_degi[i];
        g_rowstart[i] = g_incl[i] - deg + g_part[i >> 10];
        g_dinv[i] = rsqrtf(1.0f + (float)deg);
    }
}

__global__ void k_fill(const int* __restrict__ src, const int* __restrict__ dst, int E) {
    int stride = gridDim.x * blockDim.x;
    for (int e = blockIdx.x * blockDim.x + threadIdx.x; e < E; e += stride) {
        int d = dst[e];
        int pos = g_rowstart[d] + atomicAdd(&g_cursor[d], 1);
        g_csrc[pos] = src[e];
    }
}

// ---------------------------------------------------------------------------
// SGEMM: C[M,128] = A[M,128] @ B[128,128], fp32, double-buffered smem.
__global__ __launch_bounds__(256) void k_sgemm(const float* __restrict__ A,
                                               const float* __restrict__ B,
                                               float* __restrict__ C, int M) {
    __shared__ float As[2][8][128];
    __shared__ float Bs[2][8][128];
    const int tid = threadIdx.x;
    const int block_row = blockIdx.x * 128;
    const int tr = tid / 16;
    const int tc = tid % 16;
    const int aRow = tid >> 1;
    const int aCol = (tid & 1) * 4;
    const int bRow = tid >> 5;
    const int bCol = (tid & 31) * 4;
    const int gr = block_row + aRow;

    float acc[8][8];
#pragma unroll
    for (int i = 0; i < 8; i++)
#pragma unroll
        for (int j = 0; j < 8; j++) acc[i][j] = 0.0f;

    {
        float4 av = make_float4(0.f, 0.f, 0.f, 0.f);
        if (gr < M) av = *(const float4*)(A + (size_t)gr * 128 + aCol);
        As[0][aCol + 0][aRow] = av.x;
        As[0][aCol + 1][aRow] = av.y;
        As[0][aCol + 2][aRow] = av.z;
        As[0][aCol + 3][aRow] = av.w;
        *(float4*)&Bs[0][bRow][bCol] = *(const float4*)(B + (size_t)bRow * 128 + bCol);
    }
    __syncthreads();

    int buf = 0;
#pragma unroll
    for (int k0 = 0; k0 < 128; k0 += 8) {
        if (k0 + 8 < 128) {
            float4 av = make_float4(0.f, 0.f, 0.f, 0.f);
            if (gr < M) av = *(const float4*)(A + (size_t)gr * 128 + k0 + 8 + aCol);
            As[buf ^ 1][aCol + 0][aRow] = av.x;
            As[buf ^ 1][aCol + 1][aRow] = av.y;
            As[buf ^ 1][aCol + 2][aRow] = av.z;
            As[buf ^ 1][aCol + 3][aRow] = av.w;
            *(float4*)&Bs[buf ^ 1][bRow][bCol] =
                *(const float4*)(B + (size_t)(k0 + 8 + bRow) * 128 + bCol);
        }
#pragma unroll
        for (int k = 0; k < 8; k++) {
            float a[8], b[8];
#pragma unroll
            for (int i = 0; i < 8; i++) a[i] = As[buf][k][tr * 8 + i];
#pragma unroll
            for (int j = 0; j < 8; j++) b[j] = Bs[buf][k][tc * 8 + j];
#pragma unroll
            for (int i = 0; i < 8; i++)
#pragma unroll
                for (int j = 0; j < 8; j++) acc[i][j] += a[i] * b[j];
        }
        __syncthreads();
        buf ^= 1;
    }

#pragma unroll
    for (int i = 0; i < 8; i++) {
        int row = block_row + tr * 8 + i;
        if (row < M) {
            float* cp = C + (size_t)row * 128 + tc * 8;
            *(float4*)cp       = make_float4(acc[i][0], acc[i][1], acc[i][2], acc[i][3]);
            *(float4*)(cp + 4) = make_float4(acc[i][4], acc[i][5], acc[i][6], acc[i][7]);
        }
    }
}

// ---------------------------------------------------------------------------
// Warp-per-node CSR gather + fused layer-2 projection.
//   acc = h[d]*dinv[d]^2 + sum_{s in N(d)} h[s]*dinv[s]*dinv[d]
//   h1  = relu(acc + b1)
//   g_w[d] = dinv[d] * dot(h1, w2l)
__global__ void k_gather1(const float* __restrict__ h,
                          const float* __restrict__ bias, int n) {
    const int lane = threadIdx.x & 31;
    int warp = (blockIdx.x * blockDim.x + threadIdx.x) >> 5;
    int nwarps = (gridDim.x * blockDim.x) >> 5;
    float4 bv = ((const float4*)bias)[lane];
    float4 wl = ((const float4*)g_w2l)[lane];
    for (int d = warp; d < n; d += nwarps) {
        float dd = g_dinv[d];
        float4 acc = ((const float4*)(h + (size_t)d * FEAT))[lane];
        float sl = dd * dd;
        acc.x *= sl; acc.y *= sl; acc.z *= sl; acc.w *= sl;
        int r0 = g_rowstart[d];
        int r1 = r0 + g_degi[d];
        for (int r = r0; r < r1; r++) {
            int s = g_csrc[r];
            float nrm = g_dinv[s] * dd;
            float4 v = ((const float4*)(h + (size_t)s * FEAT))[lane];
            acc.x += v.x * nrm; acc.y += v.y * nrm;
            acc.z += v.z * nrm; acc.w += v.w * nrm;
        }
        acc.x = fmaxf(acc.x + bv.x, 0.f);
        acc.y = fmaxf(acc.y + bv.y, 0.f);
        acc.z = fmaxf(acc.z + bv.z, 0.f);
        acc.w = fmaxf(acc.w + bv.w, 0.f);
        float sdot = acc.x * wl.x + acc.y * wl.y + acc.z * wl.z + acc.w * wl.w;
#pragma unroll
        for (int off = 16; off > 0; off >>= 1)
            sdot += __shfl_xor_sync(0xFFFFFFFFu, sdot, off);
        if (lane == 0) g_w[d] = dd * sdot;
    }
}

// Scalar aggregation + pool: z[d] = dinv[d]*(w[d] + sum_{s} w[s]);
// gsum[batch[d]] += z[d]. Thread per node.
__global__ void k_scalar(const int* __restrict__ batch, int n) {
    int stride = gridDim.x * blockDim.x;
    for (int d = blockIdx.x * blockDim.x + threadIdx.x; d < n; d += stride) {
        float s = g_w[d];
        int r0 = g_rowstart[d];
        int r1 = r0 + g_degi[d];
        for (int r = r0; r < r1; r++) s += g_w[g_csrc[r]];
        atomicAdd(&g_gsum[batch[d]], g_dinv[d] * s);
    }
}

// out[g] = gsum[g]/max(cnt,1) + dot(b2, Wl) + bl
__global__ void k_out(const float* __restrict__ bl, float* __restrict__ out) {
    int g = blockIdx.x * blockDim.x + threadIdx.x;
    if (g < GMAX)
        out[g] = g_gsum[g] / fmaxf(g_cnt[g], 1.0f) + g_b2wl + bl[0];
}

// ---------------------------------------------------------------------------
extern "C" void kernel_launch(void* const* d_in, const int* in_sizes, int n_in,
                              void* d_out, int out_size) {
    const float* x     = (const float*)d_in[0];
    const int*   ei    = (const int*)d_in[1];
    const int*   batch = (const int*)d_in[3];
    const float* W1    = (const float*)d_in[4];
    const float* b1    = (const float*)d_in[5];
    const float* W2    = (const float*)d_in[6];
    const float* b2    = (const float*)d_in[7];
    const float* Wl    = (const float*)d_in[8];
    const float* bl    = (const float*)d_in[9];
    float* out = (float*)d_out;

    int n = in_sizes[0] / FEAT;
    int E = in_sizes[1] / 2;
    if (n > NMAX) n = NMAX;
    if (E > EMAX) E = EMAX;
    const int* src = ei;
    const int* dst = ei + E;

    float* bufA;
    cudaGetSymbolAddress((void**)&bufA, g_bufA);

    const int T = 256;
    int nBlocksN   = (n + T - 1) / T;
    int gemmBlocks = (n + 127) / 128;
    int scanBlocks = (n + 1023) / 1024;   // <= 98 for NMAX

    // CSR build + small precomputes
    k_init<<<nBlocksN, T>>>(n);
    k_hist<<<1024, T>>>(dst, E, batch, n);
    k_w2l<<<1, 128>>>(W2, Wl, b2);
    k_scan1<<<scanBlocks, 1024>>>(n);
    k_scan2<<<1, 256>>>(scanBlocks);
    k_scan3<<<nBlocksN, T>>>(n);
    k_fill<<<1024, T>>>(src, dst, E);

    // Layer 1 GEMM: x @ W1
    k_sgemm<<<gemmBlocks, T>>>(x, W1, bufA, n);

    // Feature gather + relu + fused projection onto w2l -> g_w
    k_gather1<<<2048, T>>>(bufA, b1, n);

    // Layer-2 scalar aggregation + pool
    k_scalar<<<512, T>>>(batch, n);

    // Head
    k_out<<<(GMAX + T - 1) / T, T>>>(bl, out);
}

// round 6
// speedup vs baseline: 3.8008x; 1.1647x over previous
#include <cuda_runtime.h>
#include <cuda_fp16.h>

// GCN: h1 = relu(A_hat @ (x@W1) + b1); h2 = A_hat @ (h1@W2) + b2
// out[g] = mean_i dot(h2[i], Wl) + bl
// Layer 2 is linear => with w2l = W2@Wl:
//   dot(h2[i],Wl) = (A_hat @ (h1 @ w2l))[i] + dot(b2,Wl)
// Layer-1 gather epilogue emits w[d] = dinv[d]*dot(relu(acc+b1), w2l);
// layer 2 is then a scalar CSR aggregation over w. h1 never materialized.
// x@W1 stored as fp16 to halve the L2-bound gather traffic.

#define NMAX 100000
#define EMAX 1600000
#define GMAX 512
#define FEAT 128

__device__ __half g_bufH[(size_t)NMAX * FEAT];  // x @ W1 (fp16 storage)
__device__ float g_w[NMAX];                      // dinv[i] * dot(h1[i], w2l)
__device__ float g_dinv[NMAX];
__device__ float g_w2l[FEAT];
__device__ float g_b2wl;                         // dot(b2, Wl)
__device__ float g_gsum[GMAX];
__device__ float g_cnt[GMAX];

__device__ int g_degi[NMAX];      // incoming-edge count (no self loop)
__device__ int g_rowstart[NMAX];  // CSR row offsets (atomic slot allocation)
__device__ int g_cursor[NMAX];    // absolute fill cursors
__device__ int g_csrc[EMAX];      // CSR: source node per incoming edge
__device__ int g_ctr;             // slot allocator counter

// ---------------------------------------------------------------------------
__global__ void k_init(int n) {
    int i = blockIdx.x * blockDim.x + threadIdx.x;
    if (i < n) g_degi[i] = 0;
    if (i < GMAX) { g_gsum[i] = 0.0f; g_cnt[i] = 0.0f; }
    if (i == 0) g_ctr = 0;
}

__global__ void k_hist(const int* __restrict__ dst, int E,
                       const int* __restrict__ batch, int n) {
    int stride = gridDim.x * blockDim.x;
    int t = blockIdx.x * blockDim.x + threadIdx.x;
    for (int e = t; e < E; e += stride)
        atomicAdd(&g_degi[dst[e]], 1);
    for (int i = t; i < n; i += stride)
        atomicAdd(&g_cnt[batch[i]], 1.0f);
}

// w2l = W2 @ Wl ; b2wl = dot(b2, Wl). One block, 128 threads.
__global__ __launch_bounds__(128) void k_w2l(const float* __restrict__ W2,
                                             const float* __restrict__ Wl,
                                             const float* __restrict__ b2) {
    __shared__ float wls[FEAT];
    int t = threadIdx.x;
    wls[t] = Wl[t];
    __syncthreads();
    float acc = 0.0f;
    const float* row = W2 + (size_t)t * FEAT;
#pragma unroll 8
    for (int j = 0; j < FEAT; j++) acc += row[j] * wls[j];
    g_w2l[t] = acc;
    if (t == 0) {
        float c = 0.0f;
        for (int j = 0; j < FEAT; j++) c += b2[j] * wls[j];
        g_b2wl = c;
    }
}

// CSR slot allocation (row order irrelevant — gather sums a contiguous range)
// + dinv in one pass.
__global__ void k_alloc(int n) {
    int i = blockIdx.x * blockDim.x + threadIdx.x;
    if (i < n) {
        int deg = g_degi[i];
        int rs = atomicAdd(&g_ctr, deg);
        g_rowstart[i] = rs;
        g_cursor[i] = rs;
        g_dinv[i] = rsqrtf(1.0f + (float)deg);
    }
}

__global__ void k_fill(const int* __restrict__ src, const int* __restrict__ dst, int E) {
    int stride = gridDim.x * blockDim.x;
    for (int e = blockIdx.x * blockDim.x + threadIdx.x; e < E; e += stride) {
        int pos = atomicAdd(&g_cursor[dst[e]], 1);
        g_csrc[pos] = src[e];
    }
}

// ---------------------------------------------------------------------------
// SGEMM: C[M,128] = A[M,128] @ B[128,128], fp32 math, fp16 output.
__global__ __launch_bounds__(256) void k_sgemm(const float* __restrict__ A,
                                               const float* __restrict__ B,
                                               __half* __restrict__ C, int M) {
    __shared__ float As[2][8][128];
    __shared__ float Bs[2][8][128];
    const int tid = threadIdx.x;
    const int block_row = blockIdx.x * 128;
    const int tr = tid / 16;
    const int tc = tid % 16;
    const int aRow = tid >> 1;
    const int aCol = (tid & 1) * 4;
    const int bRow = tid >> 5;
    const int bCol = (tid & 31) * 4;
    const int gr = block_row + aRow;

    float acc[8][8];
#pragma unroll
    for (int i = 0; i < 8; i++)
#pragma unroll
        for (int j = 0; j < 8; j++) acc[i][j] = 0.0f;

    {
        float4 av = make_float4(0.f, 0.f, 0.f, 0.f);
        if (gr < M) av = *(const float4*)(A + (size_t)gr * 128 + aCol);
        As[0][aCol + 0][aRow] = av.x;
        As[0][aCol + 1][aRow] = av.y;
        As[0][aCol + 2][aRow] = av.z;
        As[0][aCol + 3][aRow] = av.w;
        *(float4*)&Bs[0][bRow][bCol] = *(const float4*)(B + (size_t)bRow * 128 + bCol);
    }
    __syncthreads();

    int buf = 0;
#pragma unroll
    for (int k0 = 0; k0 < 128; k0 += 8) {
        if (k0 + 8 < 128) {
            float4 av = make_float4(0.f, 0.f, 0.f, 0.f);
            if (gr < M) av = *(const float4*)(A + (size_t)gr * 128 + k0 + 8 + aCol);
            As[buf ^ 1][aCol + 0][aRow] = av.x;
            As[buf ^ 1][aCol + 1][aRow] = av.y;
            As[buf ^ 1][aCol + 2][aRow] = av.z;
            As[buf ^ 1][aCol + 3][aRow] = av.w;
            *(float4*)&Bs[buf ^ 1][bRow][bCol] =
                *(const float4*)(B + (size_t)(k0 + 8 + bRow) * 128 + bCol);
        }
#pragma unroll
        for (int k = 0; k < 8; k++) {
            float a[8], b[8];
#pragma unroll
            for (int i = 0; i < 8; i++) a[i] = As[buf][k][tr * 8 + i];
#pragma unroll
            for (int j = 0; j < 8; j++) b[j] = Bs[buf][k][tc * 8 + j];
#pragma unroll
            for (int i = 0; i < 8; i++)
#pragma unroll
                for (int j = 0; j < 8; j++) acc[i][j] += a[i] * b[j];
        }
        __syncthreads();
        buf ^= 1;
    }

#pragma unroll
    for (int i = 0; i < 8; i++) {
        int row = block_row + tr * 8 + i;
        if (row < M) {
            __half2 hv[4];
#pragma unroll
            for (int j = 0; j < 4; j++)
                hv[j] = __floats2half2_rn(acc[i][2 * j], acc[i][2 * j + 1]);
            *(uint4*)(C + (size_t)row * 128 + tc * 8) = *(uint4*)hv;
        }
    }
}

// ---------------------------------------------------------------------------
// Warp-per-node CSR gather (fp16 rows, fp32 accumulate) + fused projection.
//   acc = h[d]*dinv[d]^2 + sum_{s in N(d)} h[s]*dinv[s]*dinv[d]
//   g_w[d] = dinv[d] * dot(relu(acc + b1), w2l)
__global__ void k_gather1(const __half* __restrict__ h,
                          const float* __restrict__ bias, int n) {
    const int lane = threadIdx.x & 31;
    int warp = (blockIdx.x * blockDim.x + threadIdx.x) >> 5;
    int nwarps = (gridDim.x * blockDim.x) >> 5;
    float4 bv = ((const float4*)bias)[lane];
    float4 wl = ((const float4*)g_w2l)[lane];
    for (int d = warp; d < n; d += nwarps) {
        float dd = g_dinv[d];
        uint2 raw = ((const uint2*)(h + (size_t)d * FEAT))[lane];
        float2 p0 = __half22float2(*(const __half2*)&raw.x);
        float2 p1 = __half22float2(*(const __half2*)&raw.y);
        float sl = dd * dd;
        float4 acc = make_float4(p0.x * sl, p0.y * sl, p1.x * sl, p1.y * sl);
        int r0 = g_rowstart[d];
        int r1 = r0 + g_degi[d];
        for (int r = r0; r < r1; r++) {
            int s = g_csrc[r];
            float nrm = g_dinv[s] * dd;
            uint2 rv = ((const uint2*)(h + (size_t)s * FEAT))[lane];
            float2 q0 = __half22float2(*(const __half2*)&rv.x);
            float2 q1 = __half22float2(*(const __half2*)&rv.y);
            acc.x += q0.x * nrm; acc.y += q0.y * nrm;
            acc.z += q1.x * nrm; acc.w += q1.y * nrm;
        }
        acc.x = fmaxf(acc.x + bv.x, 0.f);
        acc.y = fmaxf(acc.y + bv.y, 0.f);
        acc.z = fmaxf(acc.z + bv.z, 0.f);
        acc.w = fmaxf(acc.w + bv.w, 0.f);
        float sdot = acc.x * wl.x + acc.y * wl.y + acc.z * wl.z + acc.w * wl.w;
#pragma unroll
        for (int off = 16; off > 0; off >>= 1)
            sdot += __shfl_xor_sync(0xFFFFFFFFu, sdot, off);
        if (lane == 0) g_w[d] = dd * sdot;
    }
}

// Scalar aggregation + pool: gsum[batch[d]] += dinv[d]*(w[d] + sum_s w[s]).
__global__ void k_scalar(const int* __restrict__ batch, int n) {
    int stride = gridDim.x * blockDim.x;
    for (int d = blockIdx.x * blockDim.x + threadIdx.x; d < n; d += stride) {
        float s = g_w[d];
        int r0 = g_rowstart[d];
        int r1 = r0 + g_degi[d];
        for (int r = r0; r < r1; r++) s += g_w[g_csrc[r]];
        atomicAdd(&g_gsum[batch[d]], g_dinv[d] * s);
    }
}

// out[g] = gsum[g]/max(cnt,1) + dot(b2, Wl) + bl
__global__ void k_out(const float* __restrict__ bl, float* __restrict__ out) {
    int g = blockIdx.x * blockDim.x + threadIdx.x;
    if (g < GMAX)
        out[g] = g_gsum[g] / fmaxf(g_cnt[g], 1.0f) + g_b2wl + bl[0];
}

// ---------------------------------------------------------------------------
extern "C" void kernel_launch(void* const* d_in, const int* in_sizes, int n_in,
                              void* d_out, int out_size) {
    const float* x     = (const float*)d_in[0];
    const int*   ei    = (const int*)d_in[1];
    const int*   batch = (const int*)d_in[3];
    const float* W1    = (const float*)d_in[4];
    const float* b1    = (const float*)d_in[5];
    const float* W2    = (const float*)d_in[6];
    const float* b2    = (const float*)d_in[7];
    const float* Wl    = (const float*)d_in[8];
    const float* bl    = (const float*)d_in[9];
    float* out = (float*)d_out;

    int n = in_sizes[0] / FEAT;
    int E = in_sizes[1] / 2;
    if (n > NMAX) n = NMAX;
    if (E > EMAX) E = EMAX;
    const int* src = ei;
    const int* dst = ei + E;

    __half* bufH;
    cudaGetSymbolAddress((void**)&bufH, g_bufH);

    const int T = 256;
    int nBlocksN   = (n + T - 1) / T;
    int gemmBlocks = (n + 127) / 128;

    // CSR build + small precomputes
    k_init<<<nBlocksN, T>>>(n);
    k_hist<<<1024, T>>>(dst, E, batch, n);
    k_w2l<<<1, 128>>>(W2, Wl, b2);
    k_alloc<<<nBlocksN, T>>>(n);
    k_fill<<<1024, T>>>(src, dst, E);

    // Layer 1 GEMM: x @ W1 (fp32 math, fp16 output)
    k_sgemm<<<gemmBlocks, T>>>(x, W1, bufH, n);

    // Feature gather + relu + fused projection onto w2l -> g_w
    k_gather1<<<2048, T>>>(bufH, b1, n);

    // Layer-2 scalar aggregation + pool
    k_scalar<<<512, T>>>(batch, n);

    // Head
    k_out<<<(GMAX + T - 1) / T, T>>>(bl, out);
}

// round 7
// speedup vs baseline: 3.9639x; 1.0429x over previous
#include <cuda_runtime.h>
#include <cuda_fp16.h>
#include <mma.h>

using namespace nvcuda;

// GCN: h1 = relu(A_hat @ (x@W1) + b1); h2 = A_hat @ (h1@W2) + b2
// out[g] = mean_i dot(h2[i], Wl) + bl
// Layer 2 is linear => with w2l = W2@Wl:
//   dot(h2[i],Wl) = (A_hat @ (h1 @ w2l))[i] + dot(b2,Wl)
// Layer-1 gather epilogue emits w[d] = dinv[d]*dot(relu(acc+b1), w2l);
// layer 2 is a scalar CSR aggregation over w. h1 never materialized.
// x@W1 computed with fp16 HMMA (fp32 accum) and stored fp16.

#define NMAX 100000
#define EMAX 1600000
#define GMAX 512
#define FEAT 128

__device__ __half g_bufH[(size_t)NMAX * FEAT];  // x @ W1 (fp16 storage)
__device__ float g_w[NMAX];                      // dinv[i] * dot(h1[i], w2l)
__device__ float g_dinv[NMAX];
__device__ float g_w2l[FEAT];
__device__ float g_b2wl;                         // dot(b2, Wl)
__device__ float g_gsum[GMAX];
__device__ float g_cnt[GMAX];

__device__ int g_degi[NMAX];      // incoming-edge count (no self loop)
__device__ int g_rowstart[NMAX];  // CSR row offsets (atomic slot allocation)
__device__ int g_cursor[NMAX];    // absolute fill cursors
__device__ int g_csrc[EMAX];      // CSR: source node per incoming edge
__device__ int g_ctr;             // slot allocator counter

// ---------------------------------------------------------------------------
__global__ void k_init(int n) {
    int i = blockIdx.x * blockDim.x + threadIdx.x;
    if (i < n) g_degi[i] = 0;
    if (i < GMAX) { g_gsum[i] = 0.0f; g_cnt[i] = 0.0f; }
    if (i == 0) g_ctr = 0;
}

__global__ void k_hist(const int* __restrict__ dst, int E,
                       const int* __restrict__ batch, int n) {
    int stride = gridDim.x * blockDim.x;
    int t = blockIdx.x * blockDim.x + threadIdx.x;
    for (int e = t; e < E; e += stride)
        atomicAdd(&g_degi[dst[e]], 1);
    for (int i = t; i < n; i += stride)
        atomicAdd(&g_cnt[batch[i]], 1.0f);
}

// w2l = W2 @ Wl ; b2wl = dot(b2, Wl). One block, 128 threads.
__global__ __launch_bounds__(128) void k_w2l(const float* __restrict__ W2,
                                             const float* __restrict__ Wl,
                                             const float* __restrict__ b2) {
    __shared__ float wls[FEAT];
    int t = threadIdx.x;
    wls[t] = Wl[t];
    __syncthreads();
    float acc = 0.0f;
    const float* row = W2 + (size_t)t * FEAT;
#pragma unroll 8
    for (int j = 0; j < FEAT; j++) acc += row[j] * wls[j];
    g_w2l[t] = acc;
    if (t == 0) {
        float c = 0.0f;
        for (int j = 0; j < FEAT; j++) c += b2[j] * wls[j];
        g_b2wl = c;
    }
}

// CSR slot allocation (row order irrelevant) + dinv in one pass.
__global__ void k_alloc(int n) {
    int i = blockIdx.x * blockDim.x + threadIdx.x;
    if (i < n) {
        int deg = g_degi[i];
        int rs = atomicAdd(&g_ctr, deg);
        g_rowstart[i] = rs;
        g_cursor[i] = rs;
        g_dinv[i] = rsqrtf(1.0f + (float)deg);
    }
}

__global__ void k_fill(const int* __restrict__ src, const int* __restrict__ dst, int E) {
    int stride = gridDim.x * blockDim.x;
    for (int e = blockIdx.x * blockDim.x + threadIdx.x; e < E; e += stride) {
        int pos = atomicAdd(&g_cursor[dst[e]], 1);
        g_csrc[pos] = src[e];
    }
}

// ---------------------------------------------------------------------------
// HMMA GEMM: C[M,128] = fp16(A[M,128]) @ fp16(B[128,128]), fp32 accum,
// fp16 output. BM=64 rows/block, full K=128 resident in smem.
// smem: Ah 64x128 half (16KB) + Bh 128x128 half (32KB) = 48KB exactly.
__global__ __launch_bounds__(256) void k_hgemm(const float* __restrict__ A,
                                               const float* __restrict__ B,
                                               __half* __restrict__ C, int M) {
    __shared__ __half Ah[64 * 128];
    __shared__ __half Bh[128 * 128];
    const int tid = threadIdx.x;
    const int block_row = blockIdx.x * 64;

    // Load + convert B (16384 floats = 4096 float4)
    for (int i = tid; i < 4096; i += 256) {
        float4 v = ((const float4*)B)[i];
        ((__half2*)Bh)[i * 2 + 0] = __floats2half2_rn(v.x, v.y);
        ((__half2*)Bh)[i * 2 + 1] = __floats2half2_rn(v.z, v.w);
    }
    // Load + convert A tile (64 rows, 2048 float4)
    for (int i = tid; i < 2048; i += 256) {
        int row = i >> 5;          // 32 float4 per row
        int col4 = i & 31;
        float4 v = make_float4(0.f, 0.f, 0.f, 0.f);
        int gr = block_row + row;
        if (gr < M) v = ((const float4*)(A + (size_t)gr * 128))[col4];
        ((__half2*)Ah)[i * 2 + 0] = __floats2half2_rn(v.x, v.y);
        ((__half2*)Ah)[i * 2 + 1] = __floats2half2_rn(v.z, v.w);
    }
    __syncthreads();

    const int warp = tid >> 5;
    const int wm = warp >> 2;      // 0..1 -> 32 rows
    const int wn = warp & 3;       // 0..3 -> 32 cols

    wmma::fragment<wmma::accumulator, 16, 16, 16, float> acc[2][2];
#pragma unroll
    for (int i = 0; i < 2; i++)
#pragma unroll
        for (int j = 0; j < 2; j++) wmma::fill_fragment(acc[i][j], 0.0f);

#pragma unroll
    for (int k = 0; k < 128; k += 16) {
        wmma::fragment<wmma::matrix_a, 16, 16, 16, __half, wmma::row_major> a[2];
        wmma::fragment<wmma::matrix_b, 16, 16, 16, __half, wmma::row_major> b[2];
#pragma unroll
        for (int i = 0; i < 2; i++)
            wmma::load_matrix_sync(a[i], Ah + (wm * 32 + i * 16) * 128 + k, 128);
#pragma unroll
        for (int j = 0; j < 2; j++)
            wmma::load_matrix_sync(b[j], Bh + k * 128 + wn * 32 + j * 16, 128);
#pragma unroll
        for (int i = 0; i < 2; i++)
#pragma unroll
            for (int j = 0; j < 2; j++)
                wmma::mma_sync(acc[i][j], a[i], b[j], acc[i][j]);
    }
    __syncthreads();

    // Stage fp32 results in smem (reuse Bh region: 64x128 fp32 = 32KB)
    float* Cs = (float*)Bh;
#pragma unroll
    for (int i = 0; i < 2; i++)
#pragma unroll
        for (int j = 0; j < 2; j++)
            wmma::store_matrix_sync(Cs + (wm * 32 + i * 16) * 128 + wn * 32 + j * 16,
                                    acc[i][j], 128, wmma::mem_row_major);
    __syncthreads();

    // Convert + write fp16 output
    for (int i = tid; i < 2048; i += 256) {
        int row = i >> 5;
        int gr = block_row + row;
        if (gr < M) {
            float4 v = ((const float4*)Cs)[i];
            __half2 h0 = __floats2half2_rn(v.x, v.y);
            __half2 h1 = __floats2half2_rn(v.z, v.w);
            uint2 o;
            o.x = *(unsigned*)&h0;
            o.y = *(unsigned*)&h1;
            ((uint2*)(C + (size_t)gr * 128))[i & 31] = o;
        }
    }
}

// ---------------------------------------------------------------------------
// Warp-per-node CSR gather (fp16 rows, fp32 accumulate) + fused projection.
//   acc = h[d]*dinv[d]^2 + sum_{s in N(d)} h[s]*dinv[s]*dinv[d]
//   g_w[d] = dinv[d] * dot(relu(acc + b1), w2l)
__global__ void k_gather1(const __half* __restrict__ h,
                          const float* __restrict__ bias, int n) {
    const int lane = threadIdx.x & 31;
    int warp = (blockIdx.x * blockDim.x + threadIdx.x) >> 5;
    int nwarps = (gridDim.x * blockDim.x) >> 5;
    float4 bv = ((const float4*)bias)[lane];
    float4 wl = ((const float4*)g_w2l)[lane];
    for (int d = warp; d < n; d += nwarps) {
        float dd = g_dinv[d];
        uint2 raw = ((const uint2*)(h + (size_t)d * FEAT))[lane];
        float2 p0 = __half22float2(*(const __half2*)&raw.x);
        float2 p1 = __half22float2(*(const __half2*)&raw.y);
        float sl = dd * dd;
        float4 acc = make_float4(p0.x * sl, p0.y * sl, p1.x * sl, p1.y * sl);
        int r0 = g_rowstart[d];
        int r1 = r0 + g_degi[d];
        for (int r = r0; r < r1; r++) {
            int s = g_csrc[r];
            float nrm = g_dinv[s] * dd;
            uint2 rv = ((const uint2*)(h + (size_t)s * FEAT))[lane];
            float2 q0 = __half22float2(*(const __half2*)&rv.x);
            float2 q1 = __half22float2(*(const __half2*)&rv.y);
            acc.x += q0.x * nrm; acc.y += q0.y * nrm;
            acc.z += q1.x * nrm; acc.w += q1.y * nrm;
        }
        acc.x = fmaxf(acc.x + bv.x, 0.f);
        acc.y = fmaxf(acc.y + bv.y, 0.f);
        acc.z = fmaxf(acc.z + bv.z, 0.f);
        acc.w = fmaxf(acc.w + bv.w, 0.f);
        float sdot = acc.x * wl.x + acc.y * wl.y + acc.z * wl.z + acc.w * wl.w;
#pragma unroll
        for (int off = 16; off > 0; off >>= 1)
            sdot += __shfl_xor_sync(0xFFFFFFFFu, sdot, off);
        if (lane == 0) g_w[d] = dd * sdot;
    }
}

// Scalar aggregation + pool: gsum[batch[d]] += dinv[d]*(w[d] + sum_s w[s]).
__global__ void k_scalar(const int* __restrict__ batch, int n) {
    int stride = gridDim.x * blockDim.x;
    for (int d = blockIdx.x * blockDim.x + threadIdx.x; d < n; d += stride) {
        float s = g_w[d];
        int r0 = g_rowstart[d];
        int r1 = r0 + g_degi[d];
        for (int r = r0; r < r1; r++) s += g_w[g_csrc[r]];
        atomicAdd(&g_gsum[batch[d]], g_dinv[d] * s);
    }
}

// out[g] = gsum[g]/max(cnt,1) + dot(b2, Wl) + bl
__global__ void k_out(const float* __restrict__ bl, float* __restrict__ out) {
    int g = blockIdx.x * blockDim.x + threadIdx.x;
    if (g < GMAX)
        out[g] = g_gsum[g] / fmaxf(g_cnt[g], 1.0f) + g_b2wl + bl[0];
}

// ---------------------------------------------------------------------------
extern "C" void kernel_launch(void* const* d_in, const int* in_sizes, int n_in,
                              void* d_out, int out_size) {
    const float* x     = (const float*)d_in[0];
    const int*   ei    = (const int*)d_in[1];
    const int*   batch = (const int*)d_in[3];
    const float* W1    = (const float*)d_in[4];
    const float* b1    = (const float*)d_in[5];
    const float* W2    = (const float*)d_in[6];
    const float* b2    = (const float*)d_in[7];
    const float* Wl    = (const float*)d_in[8];
    const float* bl    = (const float*)d_in[9];
    float* out = (float*)d_out;

    int n = in_sizes[0] / FEAT;
    int E = in_sizes[1] / 2;
    if (n > NMAX) n = NMAX;
    if (E > EMAX) E = EMAX;
    const int* src = ei;
    const int* dst = ei + E;

    __half* bufH;
    cudaGetSymbolAddress((void**)&bufH, g_bufH);

    const int T = 256;
    int nBlocksN   = (n + T - 1) / T;
    int gemmBlocks = (n + 63) / 64;

    // CSR build + small precomputes
    k_init<<<nBlocksN, T>>>(n);
    k_hist<<<1024, T>>>(dst, E, batch, n);
    k_w2l<<<1, 128>>>(W2, Wl, b2);
    k_alloc<<<nBlocksN, T>>>(n);
    k_fill<<<1024, T>>>(src, dst, E);

    // Layer 1 GEMM: x @ W1 (fp16 HMMA, fp32 accum, fp16 output)
    k_hgemm<<<gemmBlocks, T>>>(x, W1, bufH, n);

    // Feature gather + relu + fused projection onto w2l -> g_w
    k_gather1<<<2048, T>>>(bufH, b1, n);

    // Layer-2 scalar aggregation + pool
    k_scalar<<<512, T>>>(batch, n);

    // Head
    k_out<<<(GMAX + T - 1) / T, T>>>(bl, out);
}

// round 8
// speedup vs baseline: 4.5239x; 1.1413x over previous
#include <cuda_runtime.h>
#include <cuda_fp16.h>
#include <mma.h>

using namespace nvcuda;

// GCN: h1 = relu(A_hat @ (x@W1) + b1); h2 = A_hat @ (h1@W2) + b2
// out[g] = mean_i dot(h2[i], Wl) + bl
// Layer 2 linear => w2l = W2@Wl collapses it to a scalar CSR aggregation.
// Layer-1 gather epilogue emits w[d] = dinv[d]*dot(relu(acc+b1), w2l).
// x@W1 via fp16 HMMA, stored fp16. GEMM overlapped with CSR build on a
// second stream (fork/join events inside graph capture).

#define NMAX 100000
#define EMAX 1600000
#define GMAX 512
#define FEAT 128

__device__ __half g_bufH[(size_t)NMAX * FEAT];  // x @ W1 (fp16 storage)
__device__ float g_w[NMAX];                      // dinv[i] * dot(h1[i], w2l)
__device__ float g_dinv[NMAX];
__device__ float g_w2l[FEAT];
__device__ float g_b2wl;                         // dot(b2, Wl)
__device__ float g_gsum[GMAX];
__device__ float g_cnt[GMAX];

__device__ int g_degi[NMAX];      // incoming-edge count (no self loop)
__device__ int g_rowstart[NMAX];  // CSR row offsets (atomic slot allocation)
__device__ int g_cursor[NMAX];    // absolute fill cursors
__device__ int g_csrc[EMAX];      // CSR: source node per incoming edge
__device__ int g_ctr;             // slot allocator counter

// ---------------------------------------------------------------------------
__global__ void k_init(int n) {
    int i = blockIdx.x * blockDim.x + threadIdx.x;
    if (i < n) g_degi[i] = 0;
    if (i < GMAX) { g_gsum[i] = 0.0f; g_cnt[i] = 0.0f; }
    if (i == 0) g_ctr = 0;
}

__global__ void k_hist(const int* __restrict__ dst, int E,
                       const int* __restrict__ batch, int n) {
    int stride = gridDim.x * blockDim.x;
    int t = blockIdx.x * blockDim.x + threadIdx.x;
    int E4 = E >> 2;
    const int4* d4 = (const int4*)dst;
    for (int e = t; e < E4; e += stride) {
        int4 v = d4[e];
        atomicAdd(&g_degi[v.x], 1);
        atomicAdd(&g_degi[v.y], 1);
        atomicAdd(&g_degi[v.z], 1);
        atomicAdd(&g_degi[v.w], 1);
    }
    for (int e = E4 * 4 + t; e < E; e += stride)
        atomicAdd(&g_degi[dst[e]], 1);
    for (int i = t; i < n; i += stride)
        atomicAdd(&g_cnt[batch[i]], 1.0f);
}

// w2l = W2 @ Wl ; b2wl = dot(b2, Wl). One block, 128 threads.
__global__ __launch_bounds__(128) void k_w2l(const float* __restrict__ W2,
                                             const float* __restrict__ Wl,
                                             const float* __restrict__ b2) {
    __shared__ float wls[FEAT];
    int t = threadIdx.x;
    wls[t] = Wl[t];
    __syncthreads();
    float acc = 0.0f;
    const float* row = W2 + (size_t)t * FEAT;
#pragma unroll 8
    for (int j = 0; j < FEAT; j++) acc += row[j] * wls[j];
    g_w2l[t] = acc;
    if (t == 0) {
        float c = 0.0f;
        for (int j = 0; j < FEAT; j++) c += b2[j] * wls[j];
        g_b2wl = c;
    }
}

// CSR slot allocation (row order irrelevant) + dinv in one pass.
__global__ void k_alloc(int n) {
    int i = blockIdx.x * blockDim.x + threadIdx.x;
    if (i < n) {
        int deg = g_degi[i];
        int rs = atomicAdd(&g_ctr, deg);
        g_rowstart[i] = rs;
        g_cursor[i] = rs;
        g_dinv[i] = rsqrtf(1.0f + (float)deg);
    }
}

__global__ void k_fill(const int* __restrict__ src, const int* __restrict__ dst, int E) {
    int stride = gridDim.x * blockDim.x;
    int t = blockIdx.x * blockDim.x + threadIdx.x;
    int E4 = E >> 2;
    const int4* d4 = (const int4*)dst;
    const int4* s4 = (const int4*)src;
    for (int e = t; e < E4; e += stride) {
        int4 dv = d4[e];
        int4 sv = s4[e];
        g_csrc[atomicAdd(&g_cursor[dv.x], 1)] = sv.x;
        g_csrc[atomicAdd(&g_cursor[dv.y], 1)] = sv.y;
        g_csrc[atomicAdd(&g_cursor[dv.z], 1)] = sv.z;
        g_csrc[atomicAdd(&g_cursor[dv.w], 1)] = sv.w;
    }
    for (int e = E4 * 4 + t; e < E; e += stride)
        g_csrc[atomicAdd(&g_cursor[dst[e]], 1)] = src[e];
}

// ---------------------------------------------------------------------------
// HMMA GEMM: C[M,128] = fp16(A[M,128]) @ fp16(B[128,128]), fp32 accum,
// fp16 output. BM=64 rows/block, full K=128 resident in smem (48KB).
__global__ __launch_bounds__(256) void k_hgemm(const float* __restrict__ A,
                                               const float* __restrict__ B,
                                               __half* __restrict__ C, int M) {
    __shared__ __half Ah[64 * 128];
    __shared__ __half Bh[128 * 128];
    const int tid = threadIdx.x;
    const int block_row = blockIdx.x * 64;

    for (int i = tid; i < 4096; i += 256) {
        float4 v = ((const float4*)B)[i];
        ((__half2*)Bh)[i * 2 + 0] = __floats2half2_rn(v.x, v.y);
        ((__half2*)Bh)[i * 2 + 1] = __floats2half2_rn(v.z, v.w);
    }
    for (int i = tid; i < 2048; i += 256) {
        int row = i >> 5;
        float4 v = make_float4(0.f, 0.f, 0.f, 0.f);
        int gr = block_row + row;
        if (gr < M) v = ((const float4*)(A + (size_t)gr * 128))[i & 31];
        ((__half2*)Ah)[i * 2 + 0] = __floats2half2_rn(v.x, v.y);
        ((__half2*)Ah)[i * 2 + 1] = __floats2half2_rn(v.z, v.w);
    }
    __syncthreads();

    const int warp = tid >> 5;
    const int wm = warp >> 2;
    const int wn = warp & 3;

    wmma::fragment<wmma::accumulator, 16, 16, 16, float> acc[2][2];
#pragma unroll
    for (int i = 0; i < 2; i++)
#pragma unroll
        for (int j = 0; j < 2; j++) wmma::fill_fragment(acc[i][j], 0.0f);

#pragma unroll
    for (int k = 0; k < 128; k += 16) {
        wmma::fragment<wmma::matrix_a, 16, 16, 16, __half, wmma::row_major> a[2];
        wmma::fragment<wmma::matrix_b, 16, 16, 16, __half, wmma::row_major> b[2];
#pragma unroll
        for (int i = 0; i < 2; i++)
            wmma::load_matrix_sync(a[i], Ah + (wm * 32 + i * 16) * 128 + k, 128);
#pragma unroll
        for (int j = 0; j < 2; j++)
            wmma::load_matrix_sync(b[j], Bh + k * 128 + wn * 32 + j * 16, 128);
#pragma unroll
        for (int i = 0; i < 2; i++)
#pragma unroll
            for (int j = 0; j < 2; j++)
                wmma::mma_sync(acc[i][j], a[i], b[j], acc[i][j]);
    }
    __syncthreads();

    float* Cs = (float*)Bh;
#pragma unroll
    for (int i = 0; i < 2; i++)
#pragma unroll
        for (int j = 0; j < 2; j++)
            wmma::store_matrix_sync(Cs + (wm * 32 + i * 16) * 128 + wn * 32 + j * 16,
                                    acc[i][j], 128, wmma::mem_row_major);
    __syncthreads();

    for (int i = tid; i < 2048; i += 256) {
        int row = i >> 5;
        int gr = block_row + row;
        if (gr < M) {
            float4 v = ((const float4*)Cs)[i];
            __half2 h0 = __floats2half2_rn(v.x, v.y);
            __half2 h1 = __floats2half2_rn(v.z, v.w);
            uint2 o;
            o.x = *(unsigned*)&h0;
            o.y = *(unsigned*)&h1;
            ((uint2*)(C + (size_t)gr * 128))[i & 31] = o;
        }
    }
}

// ---------------------------------------------------------------------------
// CSR gather: 2 nodes per warp, 16 lanes x uint4 (8 halves) per node row.
//   acc = h[d]*dinv[d]^2 + sum_{s in N(d)} h[s]*dinv[s]*dinv[d]
//   g_w[d] = dinv[d] * dot(relu(acc + b1), w2l)
__global__ void k_gather1(const __half* __restrict__ h,
                          const float* __restrict__ bias, int n) {
    const int lane = threadIdx.x & 31;
    const int half = lane >> 4;        // which node of the pair
    const int hl = lane & 15;          // lane within half-warp
    int warp = (blockIdx.x * blockDim.x + threadIdx.x) >> 5;
    int nwarps = (gridDim.x * blockDim.x) >> 5;

    float4 b0 = ((const float4*)bias)[hl * 2 + 0];
    float4 b1v = ((const float4*)bias)[hl * 2 + 1];
    float4 w0 = ((const float4*)g_w2l)[hl * 2 + 0];
    float4 w1 = ((const float4*)g_w2l)[hl * 2 + 1];

    for (int d = warp * 2 + half; d < n; d += nwarps * 2) {
        float dd = g_dinv[d];
        uint4 raw = ((const uint4*)(h + (size_t)d * FEAT))[hl];
        float2 p0 = __half22float2(*(const __half2*)&raw.x);
        float2 p1 = __half22float2(*(const __half2*)&raw.y);
        float2 p2 = __half22float2(*(const __half2*)&raw.z);
        float2 p3 = __half22float2(*(const __half2*)&raw.w);
        float sl = dd * dd;
        float a0 = p0.x * sl, a1 = p0.y * sl, a2 = p1.x * sl, a3 = p1.y * sl;
        float a4 = p2.x * sl, a5 = p2.y * sl, a6 = p3.x * sl, a7 = p3.y * sl;

        int r0 = g_rowstart[d];
        int r1 = r0 + g_degi[d];
        for (int r = r0; r < r1; r++) {
            int s = g_csrc[r];
            float nrm = g_dinv[s] * dd;
            uint4 rv = ((const uint4*)(h + (size_t)s * FEAT))[hl];
            float2 q0 = __half22float2(*(const __half2*)&rv.x);
            float2 q1 = __half22float2(*(const __half2*)&rv.y);
            float2 q2 = __half22float2(*(const __half2*)&rv.z);
            float2 q3 = __half22float2(*(const __half2*)&rv.w);
            a0 += q0.x * nrm; a1 += q0.y * nrm;
            a2 += q1.x * nrm; a3 += q1.y * nrm;
            a4 += q2.x * nrm; a5 += q2.y * nrm;
            a6 += q3.x * nrm; a7 += q3.y * nrm;
        }
        float sdot;
        sdot  = fmaxf(a0 + b0.x, 0.f) * w0.x;
        sdot += fmaxf(a1 + b0.y, 0.f) * w0.y;
        sdot += fmaxf(a2 + b0.z, 0.f) * w0.z;
        sdot += fmaxf(a3 + b0.w, 0.f) * w0.w;
        sdot += fmaxf(a4 + b1v.x, 0.f) * w1.x;
        sdot += fmaxf(a5 + b1v.y, 0.f) * w1.y;
        sdot += fmaxf(a6 + b1v.z, 0.f) * w1.z;
        sdot += fmaxf(a7 + b1v.w, 0.f) * w1.w;
#pragma unroll
        for (int off = 8; off > 0; off >>= 1)
            sdot += __shfl_xor_sync(0xFFFFFFFFu, sdot, off);
        if (hl == 0) g_w[d] = dd * sdot;
    }
}

// Scalar aggregation + pool: gsum[batch[d]] += dinv[d]*(w[d] + sum_s w[s]).
__global__ void k_scalar(const int* __restrict__ batch, int n) {
    int stride = gridDim.x * blockDim.x;
    for (int d = blockIdx.x * blockDim.x + threadIdx.x; d < n; d += stride) {
        float s = g_w[d];
        int r0 = g_rowstart[d];
        int r1 = r0 + g_degi[d];
        for (int r = r0; r < r1; r++) s += g_w[g_csrc[r]];
        atomicAdd(&g_gsum[batch[d]], g_dinv[d] * s);
    }
}

// out[g] = gsum[g]/max(cnt,1) + dot(b2, Wl) + bl
__global__ void k_out(const float* __restrict__ bl, float* __restrict__ out) {
    int g = blockIdx.x * blockDim.x + threadIdx.x;
    if (g < GMAX)
        out[g] = g_gsum[g] / fmaxf(g_cnt[g], 1.0f) + g_b2wl + bl[0];
}

// ---------------------------------------------------------------------------
static cudaStream_t g_s2 = nullptr;
static cudaEvent_t g_evFork = nullptr, g_evJoin = nullptr;

extern "C" void kernel_launch(void* const* d_in, const int* in_sizes, int n_in,
                              void* d_out, int out_size) {
    const float* x     = (const float*)d_in[0];
    const int*   ei    = (const int*)d_in[1];
    const int*   batch = (const int*)d_in[3];
    const float* W1    = (const float*)d_in[4];
    const float* b1    = (const float*)d_in[5];
    const float* W2    = (const float*)d_in[6];
    const float* b2    = (const float*)d_in[7];
    const float* Wl    = (const float*)d_in[8];
    const float* bl    = (const float*)d_in[9];
    float* out = (float*)d_out;

    int n = in_sizes[0] / FEAT;
    int E = in_sizes[1] / 2;
    if (n > NMAX) n = NMAX;
    if (E > EMAX) E = EMAX;
    const int* src = ei;
    const int* dst = ei + E;

    __half* bufH;
    cudaGetSymbolAddress((void**)&bufH, g_bufH);

    if (!g_s2) {
        cudaStreamCreateWithFlags(&g_s2, cudaStreamNonBlocking);
        cudaEventCreateWithFlags(&g_evFork, cudaEventDisableTiming);
        cudaEventCreateWithFlags(&g_evJoin, cudaEventDisableTiming);
    }

    const int T = 256;
    int nBlocksN   = (n + T - 1) / T;
    int gemmBlocks = (n + 63) / 64;

    // Fork: GEMM branch (depends only on x, W1 / W2, Wl, b2)
    cudaEventRecord(g_evFork, 0);
    cudaStreamWaitEvent(g_s2, g_evFork, 0);
    k_w2l<<<1, 128, 0, g_s2>>>(W2, Wl, b2);
    k_hgemm<<<gemmBlocks, T, 0, g_s2>>>(x, W1, bufH, n);
    cudaEventRecord(g_evJoin, g_s2);

    // CSR build chain on main stream (concurrent with GEMM)
    k_init<<<nBlocksN, T>>>(n);
    k_hist<<<1024, T>>>(dst, E, batch, n);
    k_alloc<<<nBlocksN, T>>>(n);
    k_fill<<<1024, T>>>(src, dst, E);

    // Join, then gather + scalar + head
    cudaStreamWaitEvent(0, g_evJoin, 0);
    k_gather1<<<2048, T>>>(bufH, b1, n);
    k_scalar<<<512, T>>>(batch, n);
    k_out<<<(GMAX + T - 1) / T, T>>>(bl, out);
}